// round 4
// baseline (speedup 1.0000x reference)
#include <cuda_runtime.h>
#include <stdint.h>

// PureAEVComputer radial AEV, fused kernel, anchor-chain Gaussians.
// 2 warps per output row (split by species pair) for occupancy.
// B=4, N=1024, 4 species x 16 shells, out width 1008 (tail zero).

#define NB 4
#define NN 1024
#define PAD 1152
#define OUTW 1008
#define RC2 27.04f
#define RCF 5.2f
#define PI_OVER_RC 0.6041524334f
#define LLCF 23.083120654223414f      // eta * log2(e), eta=16
#define KPF  12.407177351645084f      // 2 * LLC * 0.26875
#define SA 1.70625f                   // anchor A = shell 3
#define SB 3.85625f                   // anchor B = shell 11
#define ET1  (-1.6672144566273082f)
#define ET4  (-6.6688578265092330f)
#define ET9  (-15.004930109645774f)
#define ET16 (-26.675431306036931f)

__global__ void __launch_bounds__(128, 10)
aev_fused(const int* __restrict__ spw, const float* __restrict__ coords,
          float* __restrict__ out) {
    __shared__ float4        sco[PAD];
    __shared__ unsigned char sspb[NN];
    __shared__ int           wcnt[4][4];
    __shared__ int           woff[4][4];
    __shared__ int           sbase[5];
    __shared__ int           sbad;

    const int tid  = threadIdx.x;
    const int w    = tid >> 5;
    const int lane = tid & 31;
    const int b      = blockIdx.x >> 9;        // 512 blocks per batch
    const int rowblk = blockIdx.x & 511;       // 2 rows per block
    const unsigned full = 0xffffffffu;

    if (tid == 0) sbad = 0;
    for (int t = tid; t < PAD; t += 128)
        sco[t] = make_float4(1e9f, 1e9f, 1e9f, 0.f);
    __syncthreads();

    // ---- detect int64 vs int32 from first 512 elements ----
    int bad = 0;
    for (int q = tid; q < 512; q += 128) {
        int lo = spw[2 * q], hi = spw[2 * q + 1];
        if (hi != 0 || ((unsigned)lo) > 3u) bad = 1;
    }
    if (bad) atomicOr(&sbad, 1);
    __syncthreads();
    const int is64 = !sbad;

    for (int e = tid; e < NN; e += 128) {
        int sp = is64 ? spw[2 * (b * NN + e)] : spw[b * NN + e];
        sspb[e] = (unsigned char)sp;
    }
    __syncthreads();

    // ---- per-warp histogram (warp w owns elements [w*256, w*256+256)) ----
    {
        int c0 = 0, c1 = 0, c2 = 0, c3 = 0;
        for (int it = 0; it < 8; ++it) {
            int sp = sspb[w * 256 + it * 32 + lane];
            c0 += __popc(__ballot_sync(full, sp == 0));
            c1 += __popc(__ballot_sync(full, sp == 1));
            c2 += __popc(__ballot_sync(full, sp == 2));
            c3 += __popc(__ballot_sync(full, sp == 3));
        }
        if (lane == 0) {
            wcnt[w][0] = c0; wcnt[w][1] = c1; wcnt[w][2] = c2; wcnt[w][3] = c3;
        }
    }
    __syncthreads();

    if (tid == 0) {
        int basep = 0;
        for (int s = 0; s < 4; ++s) {
            sbase[s] = basep;
            int tot = 0;
            for (int ww = 0; ww < 4; ++ww) { woff[ww][s] = basep + tot; tot += wcnt[ww][s]; }
            basep += (tot + 31) & ~31;
        }
        sbase[4] = basep;
    }
    __syncthreads();

    // ---- scatter coords into species-sorted smem ----
    {
        const unsigned lt = (1u << lane) - 1u;
        int u0 = 0, u1 = 0, u2 = 0, u3 = 0;
        for (int it = 0; it < 8; ++it) {
            int e  = w * 256 + it * 32 + lane;
            int sp = sspb[e];
            unsigned m0 = __ballot_sync(full, sp == 0);
            unsigned m1 = __ballot_sync(full, sp == 1);
            unsigned m2 = __ballot_sync(full, sp == 2);
            unsigned m3 = __ballot_sync(full, sp == 3);
            int pos;
            if (sp == 0)      pos = woff[w][0] + u0 + __popc(m0 & lt);
            else if (sp == 1) pos = woff[w][1] + u1 + __popc(m1 & lt);
            else if (sp == 2) pos = woff[w][2] + u2 + __popc(m2 & lt);
            else              pos = woff[w][3] + u3 + __popc(m3 & lt);
            const float* cp = coords + (size_t)(b * NN + e) * 3;
            sco[pos] = make_float4(cp[0], cp[1], cp[2], 0.f);
            u0 += __popc(m0); u1 += __popc(m1); u2 += __popc(m2); u3 += __popc(m3);
        }
    }
    __syncthreads();

    // ---- zero output tails for both rows (floats [64,1008) = f4 [16,252)) ----
    {
        const float4 z4 = make_float4(0.f, 0.f, 0.f, 0.f);
        for (int r = 0; r < 2; ++r) {
            float4* o4 = (float4*)(out + (size_t)(b * NN + rowblk * 2 + r) * OUTW);
            for (int c = 16 + tid; c < 252; c += 128) o4[c] = z4;
        }
    }

    // =================== main compute ===================
    // warp w: row = rowblk*2 + (w>>1), species pair s0 = (w&1)*2
    const int i  = rowblk * 2 + (w >> 1);
    const int s0 = (w & 1) * 2;

    const float* cc = coords + (size_t)(b * NN + i) * 3;
    const float xi = cc[0], yi = cc[1], zi = cc[2];
    float* orow = out + (size_t)(b * NN + i) * OUTW;

    const float T1  = exp2f(ET1);
    const float T4  = exp2f(ET4);
    const float T9  = exp2f(ET9);
    const float T16 = exp2f(ET16);
    const float iT16 = exp2f(-ET16);
    const int b0 = lane & 1, b1 = (lane >> 1) & 1, b2 = (lane >> 2) & 1,
              b3 = (lane >> 3) & 1;

#pragma unroll
    for (int ss = 0; ss < 2; ++ss) {
        const int s = s0 + ss;
        float acc[16];
#pragma unroll
        for (int k = 0; k < 16; ++k) acc[k] = 0.f;

        const int en = sbase[s + 1];
        for (int t = sbase[s] + lane; t < en; t += 32) {
            float4 cj = sco[t];
            float dx = xi - cj.x, dy = yi - cj.y, dz = zi - cj.z;
            float d2 = fmaf(dx, dx, fmaf(dy, dy, dz * dz));
            bool ok = (d2 > 0.f) && (d2 <= RC2);
            float d  = d2 * rsqrtf(d2);            // NaN at d2==0
            float dm = fminf(d, RCF);              // NaN/far -> 5.2
            float fcv = fmaf(0.5f, __cosf(dm * PI_OVER_RC), 0.5f);
            float fc = ok ? fcv : 0.f;             // exact masking

            float fa = dm - SA;
            float ga = exp2f((-LLCF * fa) * fa);
            float fb = dm - SB;
            float gb = exp2f((-LLCF * fb) * fb);
            float pa = exp2f(fmaf(KPF, dm, -KPF * SA));
            float qa = exp2f(fmaf(-KPF, dm, KPF * SA));
            float pb = pa * T16;
            float qb = qa * iT16;
            float hA = fc * ga;
            float hB = fc * gb;

            acc[3]  += hA;
            acc[11] += hB;
            float h;
            h = hA * pa; acc[4]  = fmaf(h, T1,  acc[4]);
            h *= pa;     acc[5]  = fmaf(h, T4,  acc[5]);
            h *= pa;     acc[6]  = fmaf(h, T9,  acc[6]);
            h *= pa;     acc[7]  = fmaf(h, T16, acc[7]);
            h = hA * qa; acc[2]  = fmaf(h, T1,  acc[2]);
            h *= qa;     acc[1]  = fmaf(h, T4,  acc[1]);
            h *= qa;     acc[0]  = fmaf(h, T9,  acc[0]);
            h = hB * pb; acc[12] = fmaf(h, T1,  acc[12]);
            h *= pb;     acc[13] = fmaf(h, T4,  acc[13]);
            h *= pb;     acc[14] = fmaf(h, T9,  acc[14]);
            h *= pb;     acc[15] = fmaf(h, T16, acc[15]);
            h = hB * qb; acc[10] = fmaf(h, T1,  acc[10]);
            h *= qb;     acc[9]  = fmaf(h, T4,  acc[9]);
            h *= qb;     acc[8]  = fmaf(h, T9,  acc[8]);
        }

        // ---- shell-distributing butterfly reduction ----
        float v[8];
#pragma unroll
        for (int j = 0; j < 8; ++j) {
            float snd = b0 ? acc[2 * j] : acc[2 * j + 1];
            float rcv = __shfl_xor_sync(full, snd, 1);
            v[j] = (b0 ? acc[2 * j + 1] : acc[2 * j]) + rcv;
        }
        float vv[4];
#pragma unroll
        for (int j = 0; j < 4; ++j) {
            float snd = b1 ? v[2 * j] : v[2 * j + 1];
            float rcv = __shfl_xor_sync(full, snd, 2);
            vv[j] = (b1 ? v[2 * j + 1] : v[2 * j]) + rcv;
        }
        float x0, x1;
        {
            float snd = b2 ? vv[0] : vv[1];
            float rcv = __shfl_xor_sync(full, snd, 4);
            x0 = (b2 ? vv[1] : vv[0]) + rcv;
            snd = b2 ? vv[2] : vv[3];
            rcv = __shfl_xor_sync(full, snd, 4);
            x1 = (b2 ? vv[3] : vv[2]) + rcv;
        }
        float y;
        {
            float snd = b3 ? x0 : x1;
            float rcv = __shfl_xor_sync(full, snd, 8);
            y = (b3 ? x1 : x0) + rcv;
        }
        y += __shfl_xor_sync(full, y, 16);

        if (lane < 16) orow[s * 16 + lane] = y;
    }
}

extern "C" void kernel_launch(void* const* d_in, const int* in_sizes, int n_in,
                              void* d_out, int out_size) {
    (void)in_sizes; (void)n_in; (void)out_size;
    const int*   spec   = (const int*)d_in[0];
    const float* coords = (const float*)d_in[1];
    float*       out    = (float*)d_out;

    aev_fused<<<NB * (NN / 2), 128>>>(spec, coords, out);
}

// round 6
// speedup vs baseline: 1.1678x; 1.1678x over previous
#include <cuda_runtime.h>
#include <stdint.h>

// PureAEVComputer radial AEV, fused kernel, anchor-chain Gaussians.
// 256-thread blocks: 4 rows/block, 2 warps per row (split by species pair).
// B=4, N=1024, 4 species x 16 shells, out width 1008 (tail zero).

#define NB 4
#define NN 1024
#define PAD 1280                     // 1024 + 8*31 = 1272 -> pad to 1280
#define OUTW 1008
#define RC2 27.04f
#define RCF 5.2f
#define PI_OVER_RC 0.6041524334f
#define LLCF 23.083120654223414f      // eta * log2(e), eta=16
#define KPF  12.407177351645084f      // 2 * LLC * 0.26875
#define SA 1.70625f                   // anchor A = shell 3
#define SB 3.85625f                   // anchor B = shell 11
#define ET1  (-1.6672144566273082f)
#define ET4  (-6.6688578265092330f)
#define ET9  (-15.004930109645774f)
#define ET16 (-26.675431306036931f)

__global__ void __launch_bounds__(256, 5)
aev_fused(const int* __restrict__ spw, const float* __restrict__ coords,
          float* __restrict__ out) {
    __shared__ float4        sco[PAD];
    __shared__ unsigned char sspb[NN];
    __shared__ int           wcnt[8][4];
    __shared__ int           woff[8][4];
    __shared__ int           sbase[5];
    __shared__ int           sbad;

    const int tid  = threadIdx.x;
    const int w    = tid >> 5;
    const int lane = tid & 31;
    const int b      = blockIdx.x >> 8;        // 256 blocks per batch
    const int rowblk = blockIdx.x & 255;       // 4 rows per block
    const unsigned full = 0xffffffffu;

    if (tid == 0) sbad = 0;
    for (int t = tid; t < PAD; t += 256)
        sco[t] = make_float4(1e9f, 1e9f, 1e9f, 0.f);
    __syncthreads();

    // ---- detect int64 vs int32 from first 512 elements ----
    int bad = 0;
    for (int q = tid; q < 512; q += 256) {
        int lo = spw[2 * q], hi = spw[2 * q + 1];
        if (hi != 0 || ((unsigned)lo) > 3u) bad = 1;
    }
    if (bad) atomicOr(&sbad, 1);
    __syncthreads();
    const int is64 = !sbad;

    for (int e = tid; e < NN; e += 256) {
        int sp = is64 ? spw[2 * (b * NN + e)] : spw[b * NN + e];
        sspb[e] = (unsigned char)sp;
    }
    __syncthreads();

    // ---- per-warp histogram (warp w owns elements [w*128, w*128+128)) ----
    {
        int c0 = 0, c1 = 0, c2 = 0, c3 = 0;
        for (int it = 0; it < 4; ++it) {
            int sp = sspb[w * 128 + it * 32 + lane];
            c0 += __popc(__ballot_sync(full, sp == 0));
            c1 += __popc(__ballot_sync(full, sp == 1));
            c2 += __popc(__ballot_sync(full, sp == 2));
            c3 += __popc(__ballot_sync(full, sp == 3));
        }
        if (lane == 0) {
            wcnt[w][0] = c0; wcnt[w][1] = c1; wcnt[w][2] = c2; wcnt[w][3] = c3;
        }
    }
    __syncthreads();

    if (tid == 0) {
        int basep = 0;
        for (int s = 0; s < 4; ++s) {
            sbase[s] = basep;
            int tot = 0;
            for (int ww = 0; ww < 8; ++ww) { woff[ww][s] = basep + tot; tot += wcnt[ww][s]; }
            basep += (tot + 31) & ~31;
        }
        sbase[4] = basep;
    }
    __syncthreads();

    // ---- scatter coords into species-sorted smem ----
    {
        const unsigned lt = (1u << lane) - 1u;
        int u0 = 0, u1 = 0, u2 = 0, u3 = 0;
        for (int it = 0; it < 4; ++it) {
            int e  = w * 128 + it * 32 + lane;
            int sp = sspb[e];
            unsigned m0 = __ballot_sync(full, sp == 0);
            unsigned m1 = __ballot_sync(full, sp == 1);
            unsigned m2 = __ballot_sync(full, sp == 2);
            unsigned m3 = __ballot_sync(full, sp == 3);
            int pos;
            if (sp == 0)      pos = woff[w][0] + u0 + __popc(m0 & lt);
            else if (sp == 1) pos = woff[w][1] + u1 + __popc(m1 & lt);
            else if (sp == 2) pos = woff[w][2] + u2 + __popc(m2 & lt);
            else              pos = woff[w][3] + u3 + __popc(m3 & lt);
            const float* cp = coords + (size_t)(b * NN + e) * 3;
            sco[pos] = make_float4(cp[0], cp[1], cp[2], 0.f);
            u0 += __popc(m0); u1 += __popc(m1); u2 += __popc(m2); u3 += __popc(m3);
        }
    }
    __syncthreads();

    // ---- zero output tails for the 4 rows (floats [64,1008) = f4 [16,252)) ----
    {
        const float4 z4 = make_float4(0.f, 0.f, 0.f, 0.f);
        for (int r = 0; r < 4; ++r) {
            float4* o4 = (float4*)(out + (size_t)(b * NN + rowblk * 4 + r) * OUTW);
            for (int c = 16 + tid; c < 252; c += 256) o4[c] = z4;
        }
    }

    // =================== main compute ===================
    // warp w: row = rowblk*4 + (w>>1), species pair s0 = (w&1)*2
    const int i  = rowblk * 4 + (w >> 1);
    const int s0 = (w & 1) * 2;

    const float* cc = coords + (size_t)(b * NN + i) * 3;
    const float xi = cc[0], yi = cc[1], zi = cc[2];
    float* orow = out + (size_t)(b * NN + i) * OUTW;

    const float T1  = exp2f(ET1);
    const float T4  = exp2f(ET4);
    const float T9  = exp2f(ET9);
    const float T16 = exp2f(ET16);
    const float iT16 = exp2f(-ET16);
    const int b0 = lane & 1, b1 = (lane >> 1) & 1, b2 = (lane >> 2) & 1,
              b3 = (lane >> 3) & 1;

#pragma unroll
    for (int ss = 0; ss < 2; ++ss) {
        const int s = s0 + ss;
        float acc[16];
#pragma unroll
        for (int k = 0; k < 16; ++k) acc[k] = 0.f;

        const int en = sbase[s + 1];
        for (int t = sbase[s] + lane; t < en; t += 32) {
            float4 cj = sco[t];
            float dx = xi - cj.x, dy = yi - cj.y, dz = zi - cj.z;
            float d2 = fmaf(dx, dx, fmaf(dy, dy, dz * dz));
            bool ok = (d2 > 0.f) && (d2 <= RC2);
            float d  = d2 * rsqrtf(d2);            // NaN at d2==0
            float dm = fminf(d, RCF);              // NaN/far -> 5.2
            float fcv = fmaf(0.5f, __cosf(dm * PI_OVER_RC), 0.5f);
            float fc = ok ? fcv : 0.f;             // exact masking

            float fa = dm - SA;
            float ga = exp2f((-LLCF * fa) * fa);
            float fb = dm - SB;
            float gb = exp2f((-LLCF * fb) * fb);
            float pa = exp2f(fmaf(KPF, dm, -KPF * SA));
            float qa = exp2f(fmaf(-KPF, dm, KPF * SA));
            float pb = pa * T16;
            float qb = qa * iT16;
            float hA = fc * ga;
            float hB = fc * gb;

            acc[3]  += hA;
            acc[11] += hB;
            float h;
            h = hA * pa; acc[4]  = fmaf(h, T1,  acc[4]);
            h *= pa;     acc[5]  = fmaf(h, T4,  acc[5]);
            h *= pa;     acc[6]  = fmaf(h, T9,  acc[6]);
            h *= pa;     acc[7]  = fmaf(h, T16, acc[7]);
            h = hA * qa; acc[2]  = fmaf(h, T1,  acc[2]);
            h *= qa;     acc[1]  = fmaf(h, T4,  acc[1]);
            h *= qa;     acc[0]  = fmaf(h, T9,  acc[0]);
            h = hB * pb; acc[12] = fmaf(h, T1,  acc[12]);
            h *= pb;     acc[13] = fmaf(h, T4,  acc[13]);
            h *= pb;     acc[14] = fmaf(h, T9,  acc[14]);
            h *= pb;     acc[15] = fmaf(h, T16, acc[15]);
            h = hB * qb; acc[10] = fmaf(h, T1,  acc[10]);
            h *= qb;     acc[9]  = fmaf(h, T4,  acc[9]);
            h *= qb;     acc[8]  = fmaf(h, T9,  acc[8]);
        }

        // ---- shell-distributing butterfly reduction ----
        float v[8];
#pragma unroll
        for (int j = 0; j < 8; ++j) {
            float snd = b0 ? acc[2 * j] : acc[2 * j + 1];
            float rcv = __shfl_xor_sync(full, snd, 1);
            v[j] = (b0 ? acc[2 * j + 1] : acc[2 * j]) + rcv;
        }
        float vv[4];
#pragma unroll
        for (int j = 0; j < 4; ++j) {
            float snd = b1 ? v[2 * j] : v[2 * j + 1];
            float rcv = __shfl_xor_sync(full, snd, 2);
            vv[j] = (b1 ? v[2 * j + 1] : v[2 * j]) + rcv;
        }
        float x0, x1;
        {
            float snd = b2 ? vv[0] : vv[1];
            float rcv = __shfl_xor_sync(full, snd, 4);
            x0 = (b2 ? vv[1] : vv[0]) + rcv;
            snd = b2 ? vv[2] : vv[3];
            rcv = __shfl_xor_sync(full, snd, 4);
            x1 = (b2 ? vv[3] : vv[2]) + rcv;
        }
        float y;
        {
            float snd = b3 ? x0 : x1;
            float rcv = __shfl_xor_sync(full, snd, 8);
            y = (b3 ? x1 : x0) + rcv;
        }
        y += __shfl_xor_sync(full, y, 16);

        if (lane < 16) orow[s * 16 + lane] = y;
    }
}

extern "C" void kernel_launch(void* const* d_in, const int* in_sizes, int n_in,
                              void* d_out, int out_size) {
    (void)in_sizes; (void)n_in; (void)out_size;
    const int*   spec   = (const int*)d_in[0];
    const float* coords = (const float*)d_in[1];
    float*       out    = (float*)d_out;

    aev_fused<<<NB * (NN / 4), 256>>>(spec, coords, out);
}